// round 3
// baseline (speedup 1.0000x reference)
#include <cuda_runtime.h>

#define B_    128
#define H_    512
#define HG_   2048   // 4*H
#define T_    512
#define FIN   64
#define FOUT  8
#define WOUT  64
#define KT    64
#define NCTA  128
#define NTHR  512

// smem layout (dynamic): 4 A buffers + 4 W buffers (2 groups x 2 double-buffers)
#define SA_BYTES   8704                 // 32*68*4
#define SW_BYTES   16384                // 32*64*8
#define SW_BASE    (4*SA_BYTES)         // 34816
#define SMEM_TOTAL (SW_BASE + 4*SW_BYTES)  // 100352

// Persistent device state (allocation-free)
__device__ float g_h[2][3][B_][H_];   // double-buffered hidden state
__device__ float g_c[3][B_][H_];      // cell state
__device__ float g_pred[B_][FOUT];    // decoder feedback
__device__ unsigned g_cnt = 0;
__device__ volatile unsigned g_gen = 0;

typedef unsigned long long u64;

__device__ __forceinline__ u64 pack2(float a) {
    u64 r; asm("mov.b64 %0, {%1, %1};" : "=l"(r) : "f"(a)); return r;
}
__device__ __forceinline__ void fma2(u64& acc, u64 w, u64 a) {
    asm("fma.rn.f32x2 %0, %1, %2, %0;" : "+l"(acc) : "l"(w), "l"(a));
}
__device__ __forceinline__ u64 add2(u64 a, u64 b) {
    u64 r; asm("add.rn.f32x2 %0, %1, %2;" : "=l"(r) : "l"(a), "l"(b)); return r;
}
__device__ __forceinline__ float2 unpack2(u64 v) {
    float2 r; asm("mov.b64 {%0, %1}, %2;" : "=f"(r.x), "=f"(r.y) : "l"(v)); return r;
}
__device__ __forceinline__ float sigmoidf_(float x) { return 1.f / (1.f + expf(-x)); }

// ---------------------------------------------------------------------------
// Grid-wide sense-reversing barrier. All 128 CTAs are co-resident (128 < 148
// SMs, one wave). __threadfence (fence.gpu) both publishes prior stores and
// invalidates L1D (CCTL.IVALL on sm_103a), so post-barrier loads see fresh h/c.
// ---------------------------------------------------------------------------
__device__ __forceinline__ void grid_barrier() {
    __syncthreads();
    if (threadIdx.x == 0) {
        __threadfence();
        unsigned gen = g_gen;
        if (atomicAdd(&g_cnt, 1u) == NCTA - 1) {
            g_cnt = 0;
            __threadfence();
            g_gen = gen + 1;
        } else {
            while (g_gen == gen) { __nanosleep(32); }
            __threadfence();
        }
    }
    __syncthreads();
}

// ---------------------------------------------------------------------------
struct TileP { const float* A; int ars, aks, k0, kt; const float* W; int wK; };

__device__ __forceinline__ TileP tile_params(
    int ti, int nT1,
    const float* A1, int a1_rs, int a1_ks, int K1, const float* W1,
    const float* A2, const float* W2)
{
    TileP p;
    if (ti < nT1) {
        p.A = A1; p.ars = a1_rs; p.aks = a1_ks; p.k0 = ti * KT;
        p.kt = (K1 - p.k0 < KT) ? (K1 - p.k0) : KT;
        p.W = W1; p.wK = K1;
    } else {
        p.A = A2; p.ars = H_; p.aks = 1; p.k0 = (ti - nT1) * KT;
        p.kt = KT; p.W = W2; p.wK = H_;
    }
    return p;
}

// cooperative tile load by one 256-thread group
__device__ __forceinline__ void load_tile(
    const TileP p, int wtid, int j0, int b0, float* sA, float2* sW)
{
    if (p.kt == KT) {
        #pragma unroll
        for (int rep = 0; rep < 8; rep++) {
            int i = wtid + rep * 256;
            int bl = i >> 6, kk = i & 63;
            sA[bl * 68 + kk] = p.A[(b0 + bl) * p.ars + (p.k0 + kk) * p.aks];
        }
        #pragma unroll
        for (int rep = 0; rep < 8; rep++) {
            int i = wtid + rep * 256;
            int pr = i >> 6, kk = i & 63;
            int q = pr >> 3, wp = pr & 7;
            int n = q * H_ + j0 + wp * 2;
            const float* src = p.W + n * p.wK + p.k0 + kk;
            sW[pr * KT + kk] = make_float2(src[0], src[p.wK]);
        }
    } else {
        // kt == 8 (decoder layer 0), k0 == 0, 256 elements each
        int bl = wtid >> 3, kk = wtid & 7;
        sA[bl * 68 + kk] = p.A[(b0 + bl) * p.ars + kk * p.aks];
        int q = bl >> 3, wp = bl & 7;
        int n = q * H_ + j0 + wp * 2;
        const float* src = p.W + n * p.wK + kk;
        sW[bl * KT + kk] = make_float2(src[0], src[p.wK]);
    }
}

// per-thread FMA over one k-tile: 8 outputs (4 gate quadrants x j-pair), fp32x2
__device__ __forceinline__ void compute_tile(
    int kt, const float* sArow, const float2* sWb, int w, u64 acc[4])
{
    #pragma unroll 4
    for (int kk = 0; kk < kt; kk += 4) {
        float4 av = *reinterpret_cast<const float4*>(sArow + kk);
        u64 a0 = pack2(av.x), a1 = pack2(av.y), a2 = pack2(av.z), a3 = pack2(av.w);
        #pragma unroll
        for (int q = 0; q < 4; q++) {
            const ulonglong2* wv =
                reinterpret_cast<const ulonglong2*>(sWb + ((q * 8 + w) * KT + kk));
            ulonglong2 wa = wv[0];
            ulonglong2 wb = wv[1];
            fma2(acc[q], wa.x, a0);
            fma2(acc[q], wa.y, a1);
            fma2(acc[q], wb.x, a2);
            fma2(acc[q], wb.y, a3);
        }
    }
}

// one fused LSTM layer-step (GEMM + bias + cell), K striped across 2 groups
__device__ __forceinline__ void layer_step(
    char* smem, int g, int wtid, int lane, int w, int j0, int b0,
    const float* A1, int a1_rs, int a1_ks, int K1,
    const float* W1, const float* W2,
    const float* bi, const float* bh,
    int l, int np)
{
    const float* A2 = &g_h[np ^ 1][l][0][0];
    const int nT1 = (K1 + KT - 1) / KT;
    const int nT = nT1 + 8;
    const int R = (nT + 1) >> 1;

    float*  sAg[2] = { (float*)(smem + (g * 2 + 0) * SA_BYTES),
                       (float*)(smem + (g * 2 + 1) * SA_BYTES) };
    float2* sWg[2] = { (float2*)(smem + SW_BASE + (g * 2 + 0) * SW_BYTES),
                       (float2*)(smem + SW_BASE + (g * 2 + 1) * SW_BYTES) };

    u64 acc[4] = {0ull, 0ull, 0ull, 0ull};

    // preload my group's first tile (index g; nT >= 9 so always valid)
    load_tile(tile_params(g, nT1, A1, a1_rs, a1_ks, K1, W1, A2, W2),
              wtid, j0, b0, sAg[0], sWg[0]);

    for (int r = 0; r < R; r++) {
        __syncthreads();
        int nxt = 2 * (r + 1) + g;
        if (nxt < nT)
            load_tile(tile_params(nxt, nT1, A1, a1_rs, a1_ks, K1, W1, A2, W2),
                      wtid, j0, b0, sAg[(r + 1) & 1], sWg[(r + 1) & 1]);
        int cur = 2 * r + g;
        if (cur < nT) {
            int ktc = (cur < nT1) ? ((K1 - cur * KT < KT) ? K1 - cur * KT : KT) : KT;
            compute_tile(ktc, sAg[r & 1] + lane * 68, sWg[r & 1], w, acc);
        }
    }
    __syncthreads();

    // cross-group reduction (reuse smem) + cell update by group 0
    u64* red = (u64*)smem;
    if (g == 1) {
        red[wtid * 4 + 0] = acc[0]; red[wtid * 4 + 1] = acc[1];
        red[wtid * 4 + 2] = acc[2]; red[wtid * 4 + 3] = acc[3];
    }
    __syncthreads();
    if (g == 0) {
        #pragma unroll
        for (int q = 0; q < 4; q++) acc[q] = add2(acc[q], red[wtid * 4 + q]);

        float2 gI = unpack2(acc[0]);
        float2 gF = unpack2(acc[1]);
        float2 gG = unpack2(acc[2]);
        float2 gO = unpack2(acc[3]);

        float* c_st  = &g_c[l][0][0];
        float* h_out = &g_h[np][l][0][0];
        const int b = b0 + lane;
        #pragma unroll
        for (int p = 0; p < 2; p++) {
            int j = j0 + 2 * w + p;
            float vi = (p ? gI.y : gI.x) + bi[j]          + bh[j];
            float vf = (p ? gF.y : gF.x) + bi[H_ + j]     + bh[H_ + j];
            float vg = (p ? gG.y : gG.x) + bi[2 * H_ + j] + bh[2 * H_ + j];
            float vo = (p ? gO.y : gO.x) + bi[3 * H_ + j] + bh[3 * H_ + j];
            float co = c_st[b * H_ + j];
            float cn = sigmoidf_(vf) * co + sigmoidf_(vi) * tanhf(vg);
            c_st[b * H_ + j]  = cn;
            h_out[b * H_ + j] = sigmoidf_(vo) * tanhf(cn);
        }
    }
}

// ---------------------------------------------------------------------------
__global__ __launch_bounds__(NTHR, 1) void lstm_persist(
    const float* __restrict__ x,
    const float* __restrict__ eWih0, const float* __restrict__ eWih,
    const float* __restrict__ eWhh,  const float* __restrict__ ebih,
    const float* __restrict__ ebhh,
    const float* __restrict__ dWih0, const float* __restrict__ dWih,
    const float* __restrict__ dWhh,  const float* __restrict__ dbih,
    const float* __restrict__ dbhh,
    const float* __restrict__ fcw,   const float* __restrict__ fcb,
    float* __restrict__ out)
{
    extern __shared__ char smem[];
    const int tid  = threadIdx.x;
    const int g    = tid >> 8;
    const int wtid = tid & 255;
    const int lane = wtid & 31;
    const int w    = wtid >> 5;
    const int j0   = (blockIdx.x & 31) * 16;
    const int b0   = (blockIdx.x >> 5) * 32;

    // ---- init: zero h (parity 0) and c; seed decoder input ----
    {
        int gid = blockIdx.x * NTHR + tid;
        #pragma unroll
        for (int r = 0; r < 3; r++) {   // 3 * 65536 = NL*B*H exactly
            int idx = gid + r * (NCTA * NTHR);
            (&g_h[0][0][0][0])[idx] = 0.f;
            (&g_c[0][0][0])[idx]    = 0.f;
        }
        if (gid < B_ * FOUT) {
            int b = gid >> 3, f = gid & 7;
            g_pred[b][f] = x[b * (FIN * T_) + (FIN - 1) * T_ + f];
        }
    }
    grid_barrier();

    const int WS = HG_ * H_;
    int s = 0;

    // ---- encoder: 512 steps x 3 layers ----
    for (int t = 0; t < T_; ++t, ++s) {
        int np = (s & 1) ^ 1;
        layer_step(smem, g, wtid, lane, w, j0, b0,
                   x + t, FIN * T_, T_, FIN, eWih0, eWhh, ebih, ebhh, 0, np);
        grid_barrier();
        layer_step(smem, g, wtid, lane, w, j0, b0,
                   &g_h[np][0][0][0], H_, 1, H_, eWih, eWhh + WS,
                   ebih + HG_, ebhh + HG_, 1, np);
        grid_barrier();
        layer_step(smem, g, wtid, lane, w, j0, b0,
                   &g_h[np][1][0][0], H_, 1, H_, eWih + WS, eWhh + 2 * WS,
                   ebih + 2 * HG_, ebhh + 2 * HG_, 2, np);
        grid_barrier();
    }

    // ---- decoder: 64 steps x (3 layers + FC) ----
    for (int d = 0; d < WOUT; ++d, ++s) {
        int np = (s & 1) ^ 1;
        layer_step(smem, g, wtid, lane, w, j0, b0,
                   &g_pred[0][0], FOUT, 1, FOUT, dWih0, dWhh, dbih, dbhh, 0, np);
        grid_barrier();
        layer_step(smem, g, wtid, lane, w, j0, b0,
                   &g_h[np][0][0][0], H_, 1, H_, dWih, dWhh + WS,
                   dbih + HG_, dbhh + HG_, 1, np);
        grid_barrier();
        layer_step(smem, g, wtid, lane, w, j0, b0,
                   &g_h[np][1][0][0], H_, 1, H_, dWih + WS, dWhh + 2 * WS,
                   dbih + 2 * HG_, dbhh + 2 * HG_, 2, np);
        grid_barrier();

        // FC head: CTA = batch row, warps 0..7 = output features
        if (tid < 256) {
            int f  = tid >> 5;
            int ln = tid & 31;
            int b  = blockIdx.x;
            const float* hrow = &g_h[np][2][b][0];
            const float* wrow = fcw + f * H_;
            float ssum = 0.f;
            #pragma unroll 4
            for (int j = ln; j < H_; j += 32) ssum += hrow[j] * wrow[j];
            #pragma unroll
            for (int o = 16; o; o >>= 1) ssum += __shfl_down_sync(0xffffffffu, ssum, o);
            if (ln == 0) {
                float v = ssum + fcb[f];
                g_pred[b][f] = v;
                out[b * (FOUT * WOUT) + f * WOUT + d] = v;
            }
        }
        grid_barrier();
    }
}

// ---------------------------------------------------------------------------
extern "C" void kernel_launch(void* const* d_in, const int* in_sizes, int n_in,
                              void* d_out, int out_size)
{
    const float* x     = (const float*)d_in[0];
    const float* eWih0 = (const float*)d_in[1];
    const float* eWih  = (const float*)d_in[2];
    const float* eWhh  = (const float*)d_in[3];
    const float* ebih  = (const float*)d_in[4];
    const float* ebhh  = (const float*)d_in[5];
    const float* dWih0 = (const float*)d_in[6];
    const float* dWih  = (const float*)d_in[7];
    const float* dWhh  = (const float*)d_in[8];
    const float* dbih  = (const float*)d_in[9];
    const float* dbhh  = (const float*)d_in[10];
    const float* fcw   = (const float*)d_in[11];
    const float* fcb   = (const float*)d_in[12];
    float* out = (float*)d_out;

    cudaFuncSetAttribute(lstm_persist,
                         cudaFuncAttributeMaxDynamicSharedMemorySize, SMEM_TOTAL);
    lstm_persist<<<NCTA, NTHR, SMEM_TOTAL>>>(
        x, eWih0, eWih, eWhh, ebih, ebhh,
        dWih0, dWih, dWhh, dbih, dbhh, fcw, fcb, out);
}

// round 4
// speedup vs baseline: 2.5086x; 2.5086x over previous
#include <cuda_runtime.h>

#define B_    128
#define H_    512
#define HG_   2048   // 4*H
#define T_    512
#define FIN   64
#define FOUT  8
#define WOUT  64
#define KT    32
#define NCTA  128
#define NTHR  512

// dynamic smem layout
#define SAT_FLOATS (KT*32)                 // 1024 floats = 4KB per A tile
#define SW_STRIDE  36                      // padded row stride (floats)
#define SW_FLOATS  (64*SW_STRIDE)          // 2304 floats = 9216B per W tile
#define SMEM_W_OFF   (8*SAT_FLOATS*4)                  // 32768
#define SMEM_RED_OFF (SMEM_W_OFF + 8*SW_FLOATS*4)      // 106496
#define SMEM_TOTAL   (SMEM_RED_OFF + 4*64*17*8)        // 141312

// persistent device state (allocation-free)
__device__ float g_h[2][3][B_][H_];   // double-buffered hidden state
__device__ float g_c[3][B_][H_];      // cell state
__device__ float g_pred[B_][FOUT];    // decoder feedback
__device__ float g_xT[T_][B_][FIN];   // pre-transposed input
__device__ unsigned g_cnt = 0;
__device__ volatile unsigned g_gen = 0;

typedef unsigned long long u64;

__device__ __forceinline__ u64 pack2(float a) {
    u64 r; asm("mov.b64 %0, {%1, %1};" : "=l"(r) : "f"(a)); return r;
}
__device__ __forceinline__ void fma2(u64& acc, u64 w, u64 a) {
    asm("fma.rn.f32x2 %0, %1, %2, %0;" : "+l"(acc) : "l"(w), "l"(a));
}
__device__ __forceinline__ float sigmoidf_(float x) { return 1.f / (1.f + expf(-x)); }

// grid-wide sense-reversing barrier; 128 CTAs co-resident (one wave).
// __threadfence = fence.gpu => CCTL.IVALL: publishes stores + invalidates L1D.
__device__ __forceinline__ void grid_barrier() {
    __syncthreads();
    if (threadIdx.x == 0) {
        __threadfence();
        unsigned gen = g_gen;
        if (atomicAdd(&g_cnt, 1u) == NCTA - 1) {
            g_cnt = 0;
            __threadfence();
            g_gen = gen + 1;
        } else {
            while (g_gen == gen) {}
        }
        __threadfence();
    }
    __syncthreads();
}

// per-K-group barrier (128 threads), ids 1..4 (0 is __syncthreads)
__device__ __forceinline__ void group_bar(int gk) {
    asm volatile("bar.sync %0, 128;" :: "r"(gk + 1) : "memory");
}

// ---------------------------------------------------------------------------
// One fused LSTM layer-step: gates = A1@W1^T + h_prev@W2^T + bi + bh -> cell.
// CTA tile: 32 b x 16 j x 4 quadrants. 512 thr = 4 K-groups x 4 b-warps.
// Per lane: 8 b (4 packed pairs) x 2 gates (ln, ln+32) -> 8 f32x2 accs.
// ---------------------------------------------------------------------------
__device__ __noinline__ void layer_step(
    char* smem, int tid,
    const float* A1, int a1s, int K1,
    const float* W1, const float* W2,
    const float* bi, const float* bh,
    int l, int np, int j0, int b0)
{
    const int gk = tid >> 7;        // K-group 0..3
    const int wt = tid & 127;
    const int ln = wt & 31;         // lane -> gate rows ln, ln+32
    const int bg = wt >> 5;         // b-group (8 rows each)
    const float* A2 = &g_h[np ^ 1][l][0][0];

    float* sA[2] = { (float*)smem + (gk*2+0)*SAT_FLOATS,
                     (float*)smem + (gk*2+1)*SAT_FLOATS };
    float* sW[2] = { (float*)(smem + SMEM_W_OFF) + (gk*2+0)*SW_FLOATS,
                     (float*)(smem + SMEM_W_OFF) + (gk*2+1)*SW_FLOATS };

    const int nT1 = (K1 + KT - 1) / KT;
    const int nT  = nT1 + H_/KT;                 // total k-tiles
    const int myN = (nT - gk + 3) >> 2;          // my round-robin share

    u64 acc[8] = {0,0,0,0,0,0,0,0};

    auto load_tile = [&](int ti, float* dA, float* dW) {
        const float* A; const float* W; int ars, wK, k0, kt;
        if (ti < nT1) { A = A1; W = W1; ars = a1s; wK = K1; k0 = ti*KT;
                        kt = (K1 - k0 < KT) ? (K1 - k0) : KT; }
        else          { A = A2; W = W2; ars = H_;  wK = H_;  k0 = (ti-nT1)*KT; kt = KT; }
        // A tile -> transposed store sAT[k][b] (zero-pad k>=kt)
        #pragma unroll
        for (int r = 0; r < 2; r++) {
            int k4 = bg + r*4;
            float4 v = make_float4(0.f,0.f,0.f,0.f);
            if (k4*4 < kt)
                v = *(const float4*)(A + (size_t)(b0+ln)*ars + k0 + k4*4);
            dA[(k4*4+0)*32 + ln] = v.x;
            dA[(k4*4+1)*32 + ln] = v.y;
            dA[(k4*4+2)*32 + ln] = v.z;
            dA[(k4*4+3)*32 + ln] = v.w;
        }
        // W tile: 64 gate rows x kt, padded stride 36
        #pragma unroll
        for (int r = 0; r < 4; r++) {
            int idx = wt + r*128;
            int g = idx >> 3, k4 = idx & 7;
            int n = (g >> 4)*H_ + j0 + (g & 15);
            float4 v = make_float4(0.f,0.f,0.f,0.f);
            if (k4*4 < kt)
                v = *(const float4*)(W + (size_t)n*wK + k0 + k4*4);
            *(float4*)(dW + g*SW_STRIDE + k4*4) = v;
        }
    };

    load_tile(gk, sA[0], sW[0]);
    group_bar(gk);

    for (int r = 0; r < myN; r++) {
        const float* cA = sA[r & 1];
        const float* cW = sW[r & 1];
        if (r + 1 < myN) load_tile(gk + (r+1)*4, sA[(r+1)&1], sW[(r+1)&1]);

        const float* wr1 = cW + ln*SW_STRIDE;
        const float* wr2 = cW + (ln+32)*SW_STRIDE;
        const float* ar  = cA + bg*8;
        #pragma unroll 4
        for (int kk = 0; kk < KT; kk += 4) {
            float4 w1 = *(const float4*)(wr1 + kk);
            float4 w2 = *(const float4*)(wr2 + kk);
            u64 W1p[4] = {pack2(w1.x), pack2(w1.y), pack2(w1.z), pack2(w1.w)};
            u64 W2p[4] = {pack2(w2.x), pack2(w2.y), pack2(w2.z), pack2(w2.w)};
            #pragma unroll
            for (int k = 0; k < 4; k++) {
                ulonglong2 aA = *(const ulonglong2*)(ar + (kk+k)*32);
                ulonglong2 aB = *(const ulonglong2*)(ar + (kk+k)*32 + 4);
                fma2(acc[0], W1p[k], aA.x);
                fma2(acc[1], W1p[k], aA.y);
                fma2(acc[2], W1p[k], aB.x);
                fma2(acc[3], W1p[k], aB.y);
                fma2(acc[4], W2p[k], aA.x);
                fma2(acc[5], W2p[k], aA.y);
                fma2(acc[6], W2p[k], aB.x);
                fma2(acc[7], W2p[k], aB.y);
            }
        }
        group_bar(gk);
    }

    // cross-K-group reduction via smem (padded to kill bank conflicts)
    u64* red = (u64*)(smem + SMEM_RED_OFF);
    u64* rg  = red + (size_t)gk*64*17;
    #pragma unroll
    for (int bp = 0; bp < 4; bp++) {
        rg[ln*17      + bg*4 + bp] = acc[bp];
        rg[(ln+32)*17 + bg*4 + bp] = acc[4+bp];
    }
    __syncthreads();

    // cell phase: thread -> (b_l = tid>>4, j_l = tid&15); coalesced h/c I/O
    {
        const float* redf = (const float*)red;
        int j_l = tid & 15;
        int b_l = tid >> 4;
        int bp = b_l >> 1, half = b_l & 1;
        float gate[4];
        #pragma unroll
        for (int q = 0; q < 4; q++) {
            int g = q*16 + j_l;
            float s = 0.f;
            #pragma unroll
            for (int gg = 0; gg < 4; gg++)
                s += redf[((gg*64 + g)*17 + bp)*2 + half];
            int n = q*H_ + j0 + j_l;
            gate[q] = s + bi[n] + bh[n];
        }
        int b = b0 + b_l, j = j0 + j_l;
        float co = g_c[l][b][j];
        float cn = sigmoidf_(gate[1]) * co + sigmoidf_(gate[0]) * tanhf(gate[2]);
        g_c[l][b][j] = cn;
        g_h[np][l][b][j] = sigmoidf_(gate[3]) * tanhf(cn);
    }
}

// ---------------------------------------------------------------------------
__global__ __launch_bounds__(NTHR, 1) void lstm_persist(
    const float* __restrict__ x,
    const float* __restrict__ eWih0, const float* __restrict__ eWih,
    const float* __restrict__ eWhh,  const float* __restrict__ ebih,
    const float* __restrict__ ebhh,
    const float* __restrict__ dWih0, const float* __restrict__ dWih,
    const float* __restrict__ dWhh,  const float* __restrict__ dbih,
    const float* __restrict__ dbhh,
    const float* __restrict__ fcw,   const float* __restrict__ fcb,
    float* __restrict__ out)
{
    extern __shared__ char smem[];
    const int tid = threadIdx.x;
    const int j0  = (blockIdx.x & 31) * 16;
    const int b0  = (blockIdx.x >> 5) * 32;

    // ---- init: zero h/c, seed decoder input, pre-transpose x ----
    {
        int gid = blockIdx.x * NTHR + tid;
        #pragma unroll
        for (int r = 0; r < 3; r++) {
            int idx = gid + r * (NCTA * NTHR);
            (&g_h[0][0][0][0])[idx] = 0.f;
            (&g_c[0][0][0])[idx]    = 0.f;
        }
        if (gid < B_ * FOUT) {
            int b = gid >> 3, f = gid & 7;
            g_pred[b][f] = x[(size_t)b * (FIN * T_) + (size_t)(FIN - 1) * T_ + f];
        }
        for (int i = gid; i < T_ * B_ * FIN; i += NCTA * NTHR) {
            int t = i >> 13, rem = i & 8191;
            int b = rem >> 6, k = rem & 63;
            (&g_xT[0][0][0])[i] = x[(size_t)b * (FIN * T_) + (size_t)k * T_ + t];
        }
    }
    grid_barrier();

    const int WS = HG_ * H_;
    int s = 0;

    // ---- encoder ----
    for (int t = 0; t < T_; ++t, ++s) {
        int np = (s & 1) ^ 1;
        layer_step(smem, tid, &g_xT[t][0][0], FIN, FIN,
                   eWih0, eWhh, ebih, ebhh, 0, np, j0, b0);
        grid_barrier();
        layer_step(smem, tid, &g_h[np][0][0][0], H_, H_,
                   eWih, eWhh + WS, ebih + HG_, ebhh + HG_, 1, np, j0, b0);
        grid_barrier();
        layer_step(smem, tid, &g_h[np][1][0][0], H_, H_,
                   eWih + WS, eWhh + 2*WS, ebih + 2*HG_, ebhh + 2*HG_, 2, np, j0, b0);
        grid_barrier();
    }

    // ---- decoder ----
    for (int d = 0; d < WOUT; ++d, ++s) {
        int np = (s & 1) ^ 1;
        layer_step(smem, tid, &g_pred[0][0], FOUT, FOUT,
                   dWih0, dWhh, dbih, dbhh, 0, np, j0, b0);
        grid_barrier();
        layer_step(smem, tid, &g_h[np][0][0][0], H_, H_,
                   dWih, dWhh + WS, dbih + HG_, dbhh + HG_, 1, np, j0, b0);
        grid_barrier();
        layer_step(smem, tid, &g_h[np][1][0][0], H_, H_,
                   dWih + WS, dWhh + 2*WS, dbih + 2*HG_, dbhh + 2*HG_, 2, np, j0, b0);
        grid_barrier();

        if (tid < 256) {   // FC head: CTA = batch row b = blockIdx.x
            int f = tid >> 5, lnn = tid & 31, b = blockIdx.x;
            const float* hrow = &g_h[np][2][b][0];
            const float* wrow = fcw + f * H_;
            float ssum = 0.f;
            #pragma unroll 4
            for (int j = lnn; j < H_; j += 32) ssum += hrow[j] * wrow[j];
            #pragma unroll
            for (int o = 16; o; o >>= 1) ssum += __shfl_down_sync(0xffffffffu, ssum, o);
            if (lnn == 0) {
                float v = ssum + fcb[f];
                g_pred[b][f] = v;
                out[(size_t)b * (FOUT * WOUT) + f * WOUT + d] = v;
            }
        }
        grid_barrier();
    }
}

// ---------------------------------------------------------------------------
extern "C" void kernel_launch(void* const* d_in, const int* in_sizes, int n_in,
                              void* d_out, int out_size)
{
    const float* x     = (const float*)d_in[0];
    const float* eWih0 = (const float*)d_in[1];
    const float* eWih  = (const float*)d_in[2];
    const float* eWhh  = (const float*)d_in[3];
    const float* ebih  = (const float*)d_in[4];
    const float* ebhh  = (const float*)d_in[5];
    const float* dWih0 = (const float*)d_in[6];
    const float* dWih  = (const float*)d_in[7];
    const float* dWhh  = (const float*)d_in[8];
    const float* dbih  = (const float*)d_in[9];
    const float* dbhh  = (const float*)d_in[10];
    const float* fcw   = (const float*)d_in[11];
    const float* fcb   = (const float*)d_in[12];
    float* out = (float*)d_out;

    cudaFuncSetAttribute(lstm_persist,
                         cudaFuncAttributeMaxDynamicSharedMemorySize, SMEM_TOTAL);
    lstm_persist<<<NCTA, NTHR, SMEM_TOTAL>>>(
        x, eWih0, eWih, eWhh, ebih, ebhh,
        dWih0, dWih, dWhh, dbih, dbhh, fcw, fcb, out);
}